// round 6
// baseline (speedup 1.0000x reference)
#include <cuda_runtime.h>

#define D        128
#define MAX_N    50000
#define TILE_M   64          // node rows per MLP block
#define MLP_THREADS 256

// Scratch for aggregated messages (static __device__ globals: allowed, no cudaMalloc)
__device__ float g_mi[MAX_N * D];
__device__ float g_mo[MAX_N * D];
__device__ int   g_idx_is64;   // 1 -> edge_index buffer is int64, 0 -> int32

// ---------------------------------------------------------------------------
// Packed f32x2 helpers (Blackwell sm_100a)
// ---------------------------------------------------------------------------
__device__ __forceinline__ unsigned long long fma2(unsigned long long a,
                                                   unsigned long long b,
                                                   unsigned long long c) {
    unsigned long long d;
    asm("fma.rn.f32x2 %0, %1, %2, %3;" : "=l"(d) : "l"(a), "l"(b), "l"(c));
    return d;
}
__device__ __forceinline__ unsigned long long pack2(float lo, float hi) {
    unsigned long long d;
    asm("mov.b64 %0, {%1, %2};" : "=l"(d) : "f"(lo), "f"(hi));
    return d;
}
__device__ __forceinline__ float2 unpack2(unsigned long long v) {
    float2 r;
    asm("mov.b64 {%0, %1}, %2;" : "=f"(r.x), "=f"(r.y) : "l"(v));
    return r;
}

// ---------------------------------------------------------------------------
// Kernel 0: detect edge_index dtype (int64 vs int32-narrowed by harness).
// ---------------------------------------------------------------------------
__global__ void detect_idx_kernel(const void* __restrict__ eidx, int E, int N) {
    if (threadIdx.x != 0 || blockIdx.x != 0) return;
    const long long* p64 = (const long long*)eidx;
    int stride = E / 64; if (stride < 1) stride = 1;
    int ok = 1;
    for (int i = 0; i < 64; ++i) {
        long long v = p64[(long long)i * stride];
        if (v < 0 || v >= N) { ok = 0; break; }
    }
    g_idx_is64 = ok;
}

// ---------------------------------------------------------------------------
// Kernel 1: zero the message buffers (float4 stores)
// ---------------------------------------------------------------------------
__global__ void zero_kernel(int n4) {
    int i = blockIdx.x * blockDim.x + threadIdx.x;
    if (i < n4) {
        float4 z = make_float4(0.f, 0.f, 0.f, 0.f);
        reinterpret_cast<float4*>(g_mi)[i] = z;
        reinterpret_cast<float4*>(g_mo)[i] = z;
    }
}

// ---------------------------------------------------------------------------
// Kernel 2: edge scatter. One warp per edge; lane l owns floats [4l,4l+4).
//   mi[dst] += e * x[src];  mo[src] += e * x[dst]
// ---------------------------------------------------------------------------
__device__ __forceinline__ void red_add_v4(float* p, float a, float b, float c, float d) {
    asm volatile("red.global.add.v4.f32 [%0], {%1, %2, %3, %4};"
                 :: "l"(p), "f"(a), "f"(b), "f"(c), "f"(d) : "memory");
}

__global__ void scatter_kernel(const float* __restrict__ x,
                               const float* __restrict__ ew,
                               const void* __restrict__ eidx,
                               int E, int N) {
    int gtid = blockIdx.x * blockDim.x + threadIdx.x;
    int edge = gtid >> 5;
    int lane = threadIdx.x & 31;
    if (edge >= E) return;

    int src, dst;
    if (g_idx_is64) {
        const long long* p = (const long long*)eidx;
        src = (int)p[edge];
        dst = (int)p[(size_t)E + edge];
    } else {
        const int* p = (const int*)eidx;
        src = p[edge];
        dst = p[(size_t)E + edge];
    }
    src = min(max(src, 0), N - 1);
    dst = min(max(dst, 0), N - 1);

    float w = ew[edge];

    const float4 vs = reinterpret_cast<const float4*>(x + (size_t)src * D)[lane];
    const float4 vd = reinterpret_cast<const float4*>(x + (size_t)dst * D)[lane];

    float* pi = g_mi + (size_t)dst * D + lane * 4;
    float* po = g_mo + (size_t)src * D + lane * 4;

    red_add_v4(pi, w * vs.x, w * vs.y, w * vs.z, w * vs.w);
    red_add_v4(po, w * vd.x, w * vd.y, w * vd.z, w * vd.w);
}

// ---------------------------------------------------------------------------
// Kernel 3: fused 4-layer MLP, column-packed f32x2 FMA.
//   sW: plain row-major 128x128 fp32 (64 KB). sH: 64x128 fp32 (32 KB).
//   Thread (cg = tid&15, rg = tid>>4) owns rows [4rg,4rg+4) x cols [8cg,8cg+8).
//   acc u64 = packed (out[c], out[c+1]) -> 32 outputs in 32 registers.
//   Per k: 2x LDS.128 (4 packed col-pairs) + 4 scalar LDS (a) + 4 splats
//          + 16 fma.rn.f32x2   (26 issues for 32 FMA lanes).
// ---------------------------------------------------------------------------
__global__ __launch_bounds__(MLP_THREADS)
void mlp_kernel(const float* __restrict__ x,
                const float* __restrict__ W1, const float* __restrict__ b1,
                const float* __restrict__ W2, const float* __restrict__ b2,
                const float* __restrict__ W3, const float* __restrict__ b3,
                const float* __restrict__ W4, const float* __restrict__ b4,
                float* __restrict__ out, int N) {
    extern __shared__ float smem[];
    float* sW = smem;            // 128*128 floats = 64 KB (row-major)
    float* sH = smem + D * D;    // 64*128  floats = 32 KB

    const int tid = threadIdx.x;
    const int cg  = tid & 15;    // col group: cols [8*cg, 8*cg+8)
    const int rg  = tid >> 4;    // row group: rows [4*rg, 4*rg+4)
    const int r0  = blockIdx.x * TILE_M;

    unsigned long long acc[4][4];

    // --- cooperative loaders ---------------------------------------------
    auto loadW = [&](const float* __restrict__ W) {
        const float4* w4 = reinterpret_cast<const float4*>(W);
        float4* s4 = reinterpret_cast<float4*>(sW);
        #pragma unroll
        for (int i = 0; i < (D * D / 4) / MLP_THREADS; ++i)
            s4[tid + i * MLP_THREADS] = w4[tid + i * MLP_THREADS];
    };
    auto loadH = [&](const float* __restrict__ src) {
        float4* s4 = reinterpret_cast<float4*>(sH);
        #pragma unroll
        for (int i = 0; i < (TILE_M * D / 4) / MLP_THREADS; ++i) {
            int idx = tid + i * MLP_THREADS;
            int row = idx >> 5;
            int col = idx & 31;
            int gr  = r0 + row;
            float4 v = make_float4(0.f, 0.f, 0.f, 0.f);
            if (gr < N)
                v = reinterpret_cast<const float4*>(src + (size_t)gr * D)[col];
            s4[idx] = v;
        }
    };
    auto initBias = [&](const float* __restrict__ b) {
        #pragma unroll
        for (int j = 0; j < 4; ++j) {
            float2 bj = *reinterpret_cast<const float2*>(b + 8 * cg + 2 * j);
            unsigned long long bp = pack2(bj.x, bj.y);
            #pragma unroll
            for (int r = 0; r < 4; ++r) acc[r][j] = bp;
        }
    };

    // --- packed register-tiled 64x128x128 GEMM accumulate -----------------
    auto gemm_acc = [&]() {
        #pragma unroll 2
        for (int k = 0; k < D; ++k) {
            // 8 weights = 4 packed col-pairs, straight from row-major sW
            ulonglong2 wA = *reinterpret_cast<const ulonglong2*>(sW + k * D + 8 * cg);
            ulonglong2 wB = *reinterpret_cast<const ulonglong2*>(sW + k * D + 8 * cg + 4);
            #pragma unroll
            for (int r = 0; r < 4; ++r) {
                float a = sH[(rg * 4 + r) * D + k];   // warp-broadcast
                unsigned long long aa = pack2(a, a);
                acc[r][0] = fma2(aa, wA.x, acc[r][0]);
                acc[r][1] = fma2(aa, wA.y, acc[r][1]);
                acc[r][2] = fma2(aa, wB.x, acc[r][2]);
                acc[r][3] = fma2(aa, wB.y, acc[r][3]);
            }
        }
    };

    auto epilogue_smem = [&]() {
        #pragma unroll
        for (int r = 0; r < 4; ++r)
            #pragma unroll
            for (int j = 0; j < 4; ++j) {
                float2 s = unpack2(acc[r][j]);
                float2 v = make_float2(tanhf(s.x), tanhf(s.y));
                *reinterpret_cast<float2*>(sH + (rg * 4 + r) * D + 8 * cg + 2 * j) = v;
            }
    };

    // ====================== Layer 1: [mi, mo, x] @ W1 =====================
    initBias(b1);
    #pragma unroll 1
    for (int p = 0; p < 3; ++p) {
        __syncthreads();                         // prior sW/sH reads complete
        loadH(p == 0 ? (const float*)g_mi : p == 1 ? (const float*)g_mo : x);
        loadW(W1 + (size_t)p * D * D);
        __syncthreads();
        gemm_acc();
    }
    __syncthreads();                             // all sH reads done
    epilogue_smem();

    // ====================== Layers 2..4 ===================================
    const float* Ws[3] = { W2, W3, W4 };
    const float* bs[3] = { b2, b3, b4 };
    #pragma unroll 1
    for (int l = 0; l < 3; ++l) {
        __syncthreads();                         // sH writes visible, prev sW reads done
        loadW(Ws[l]);
        __syncthreads();
        initBias(bs[l]);
        gemm_acc();
        __syncthreads();                         // all sH/sW reads done
        if (l < 2) {
            epilogue_smem();
        } else {
            #pragma unroll
            for (int r = 0; r < 4; ++r) {
                int gr = r0 + rg * 4 + r;
                if (gr < N)
                    #pragma unroll
                    for (int j = 0; j < 4; ++j) {
                        float2 s = unpack2(acc[r][j]);
                        float2 v = make_float2(tanhf(s.x), tanhf(s.y));
                        *reinterpret_cast<float2*>(out + (size_t)gr * D + 8 * cg + 2 * j) = v;
                    }
            }
        }
    }
}

// ---------------------------------------------------------------------------
// Host launcher (graph-capturable: kernel launches only)
// ---------------------------------------------------------------------------
extern "C" void kernel_launch(void* const* d_in, const int* in_sizes, int n_in,
                              void* d_out, int out_size) {
    const float* x    = (const float*)d_in[0];
    const float* ew   = (const float*)d_in[1];
    const void*  eidx = d_in[2];
    const float* W1   = (const float*)d_in[3];
    const float* b1   = (const float*)d_in[4];
    const float* W2   = (const float*)d_in[5];
    const float* b2   = (const float*)d_in[6];
    const float* W3   = (const float*)d_in[7];
    const float* b3   = (const float*)d_in[8];
    const float* W4   = (const float*)d_in[9];
    const float* b4   = (const float*)d_in[10];
    float*       out  = (float*)d_out;

    const int N = in_sizes[0] / D;        // 50000
    const int E = in_sizes[2] / 2;        // 800000

    // 0) detect index dtype
    detect_idx_kernel<<<1, 32>>>(eidx, E, N);

    // 1) zero message buffers
    {
        int n4 = N * D / 4;
        zero_kernel<<<(n4 + 255) / 256, 256>>>(n4);
    }

    // 2) edge scatter: one warp per edge
    {
        long long total = (long long)E * 32;
        int blocks = (int)((total + 255) / 256);
        scatter_kernel<<<blocks, 256>>>(x, ew, eidx, E, N);
    }

    // 3) fused MLP
    {
        const int smem = (D * D + TILE_M * D) * (int)sizeof(float);  // 98304 B
        cudaFuncSetAttribute(mlp_kernel,
                             cudaFuncAttributeMaxDynamicSharedMemorySize, smem);
        int blocks = (N + TILE_M - 1) / TILE_M;                      // 782
        mlp_kernel<<<blocks, MLP_THREADS, smem>>>(x, W1, b1, W2, b2,
                                                  W3, b3, W4, b4, out, N);
    }
}

// round 7
// speedup vs baseline: 1.4289x; 1.4289x over previous
#include <cuda_runtime.h>

#define D        128
#define MAX_N    50000
#define TILE_M   64          // node rows per MLP block
#define MLP_THREADS 256

// Scratch for aggregated messages (static __device__ globals: allowed, no cudaMalloc)
__device__ float g_mi[MAX_N * D];
__device__ float g_mo[MAX_N * D];
__device__ int   g_idx_is64;   // 1 -> edge_index buffer is int64, 0 -> int32

// ---------------------------------------------------------------------------
// Packed f32x2 helpers (Blackwell sm_100a)
// ---------------------------------------------------------------------------
__device__ __forceinline__ unsigned long long fma2(unsigned long long a,
                                                   unsigned long long b,
                                                   unsigned long long c) {
    unsigned long long d;
    asm("fma.rn.f32x2 %0, %1, %2, %3;" : "=l"(d) : "l"(a), "l"(b), "l"(c));
    return d;
}
__device__ __forceinline__ unsigned long long pack2(float lo, float hi) {
    unsigned long long d;
    asm("mov.b64 %0, {%1, %2};" : "=l"(d) : "f"(lo), "f"(hi));
    return d;
}
__device__ __forceinline__ float2 unpack2(unsigned long long v) {
    float2 r;
    asm("mov.b64 {%0, %1}, %2;" : "=f"(r.x), "=f"(r.y) : "l"(v));
    return r;
}

// ---------------------------------------------------------------------------
// Kernel 0: detect edge_index dtype (int64 vs int32-narrowed by harness).
// ---------------------------------------------------------------------------
__global__ void detect_idx_kernel(const void* __restrict__ eidx, int E, int N) {
    if (threadIdx.x != 0 || blockIdx.x != 0) return;
    const long long* p64 = (const long long*)eidx;
    int stride = E / 64; if (stride < 1) stride = 1;
    int ok = 1;
    for (int i = 0; i < 64; ++i) {
        long long v = p64[(long long)i * stride];
        if (v < 0 || v >= N) { ok = 0; break; }
    }
    g_idx_is64 = ok;
}

// ---------------------------------------------------------------------------
// Kernel 1: zero the message buffers (float4 stores)
// ---------------------------------------------------------------------------
__global__ void zero_kernel(int n4) {
    int i = blockIdx.x * blockDim.x + threadIdx.x;
    if (i < n4) {
        float4 z = make_float4(0.f, 0.f, 0.f, 0.f);
        reinterpret_cast<float4*>(g_mi)[i] = z;
        reinterpret_cast<float4*>(g_mo)[i] = z;
    }
}

// ---------------------------------------------------------------------------
// Kernel 2: edge scatter. One warp per edge; lane l owns floats [4l,4l+4).
//   mi[dst] += e * x[src];  mo[src] += e * x[dst]
// ---------------------------------------------------------------------------
__device__ __forceinline__ void red_add_v4(float* p, float a, float b, float c, float d) {
    asm volatile("red.global.add.v4.f32 [%0], {%1, %2, %3, %4};"
                 :: "l"(p), "f"(a), "f"(b), "f"(c), "f"(d) : "memory");
}

__global__ void scatter_kernel(const float* __restrict__ x,
                               const float* __restrict__ ew,
                               const void* __restrict__ eidx,
                               int E, int N) {
    int gtid = blockIdx.x * blockDim.x + threadIdx.x;
    int edge = gtid >> 5;
    int lane = threadIdx.x & 31;
    if (edge >= E) return;

    int src, dst;
    if (g_idx_is64) {
        const long long* p = (const long long*)eidx;
        src = (int)p[edge];
        dst = (int)p[(size_t)E + edge];
    } else {
        const int* p = (const int*)eidx;
        src = p[edge];
        dst = p[(size_t)E + edge];
    }
    src = min(max(src, 0), N - 1);
    dst = min(max(dst, 0), N - 1);

    float w = ew[edge];

    const float4 vs = reinterpret_cast<const float4*>(x + (size_t)src * D)[lane];
    const float4 vd = reinterpret_cast<const float4*>(x + (size_t)dst * D)[lane];

    float* pi = g_mi + (size_t)dst * D + lane * 4;
    float* po = g_mo + (size_t)src * D + lane * 4;

    red_add_v4(pi, w * vs.x, w * vs.y, w * vs.z, w * vs.w);
    red_add_v4(po, w * vd.x, w * vd.y, w * vd.z, w * vd.w);
}

// ---------------------------------------------------------------------------
// Kernel 3: fused 4-layer MLP — R4 layout, column-packed f32x2 inner loop.
//   sW row-major 128x128 fp32 (64 KB), sH 64x128 fp32 (32 KB).
//   Thread (cx = tid&31, ry = tid>>5) owns rows [8ry,8ry+8) x cols [4cx,4cx+4).
//   Warp weight load: LDS.128 at k*D + 4*cx -> 32 lanes x 16B contiguous 512B,
//   conflict-free; gives 2 packed col-pairs per thread.
//   Activation: single-address scalar LDS (warp broadcast), splat via mov.b64.
//   Per k per thread: 1 LDS.128 + 8 LDS + 8 mov + 16 fma2 = 33 issues (R4: 41).
// ---------------------------------------------------------------------------
__global__ __launch_bounds__(MLP_THREADS)
void mlp_kernel(const float* __restrict__ x,
                const float* __restrict__ W1, const float* __restrict__ b1,
                const float* __restrict__ W2, const float* __restrict__ b2,
                const float* __restrict__ W3, const float* __restrict__ b3,
                const float* __restrict__ W4, const float* __restrict__ b4,
                float* __restrict__ out, int N) {
    extern __shared__ float smem[];
    float* sW = smem;            // 128*128 floats = 64 KB (row-major)
    float* sH = smem + D * D;    // 64*128  floats = 32 KB

    const int tid = threadIdx.x;
    const int cx  = tid & 31;    // column group: cols [4*cx, 4*cx+4)
    const int ry  = tid >> 5;    // row group:    rows [8*ry, 8*ry+8)
    const int r0  = blockIdx.x * TILE_M;

    unsigned long long acc[8][2];    // packed (c, c+1) and (c+2, c+3) per row

    // --- cooperative loaders (identical to R4) -----------------------------
    auto loadW = [&](const float* __restrict__ W) {
        const float4* w4 = reinterpret_cast<const float4*>(W);
        float4* s4 = reinterpret_cast<float4*>(sW);
        #pragma unroll
        for (int i = 0; i < (D * D / 4) / MLP_THREADS; ++i)
            s4[tid + i * MLP_THREADS] = w4[tid + i * MLP_THREADS];
    };
    auto loadH = [&](const float* __restrict__ src) {
        float4* s4 = reinterpret_cast<float4*>(sH);
        #pragma unroll
        for (int i = 0; i < (TILE_M * D / 4) / MLP_THREADS; ++i) {
            int idx = tid + i * MLP_THREADS;
            int row = idx >> 5;
            int col = idx & 31;
            int gr  = r0 + row;
            float4 v = make_float4(0.f, 0.f, 0.f, 0.f);
            if (gr < N)
                v = reinterpret_cast<const float4*>(src + (size_t)gr * D)[col];
            s4[idx] = v;
        }
    };
    auto initBias = [&](const float* __restrict__ b) {
        float4 bv = *reinterpret_cast<const float4*>(b + 4 * cx);
        unsigned long long b0 = pack2(bv.x, bv.y);
        unsigned long long b1p = pack2(bv.z, bv.w);
        #pragma unroll
        for (int r = 0; r < 8; ++r) { acc[r][0] = b0; acc[r][1] = b1p; }
    };

    // --- packed register-tiled 64x128x128 GEMM accumulate ------------------
    auto gemm_acc = [&]() {
        #pragma unroll 4
        for (int k = 0; k < D; ++k) {
            // conflict-free: 32 lanes x 16B contiguous over the 512B row
            ulonglong2 w = *reinterpret_cast<const ulonglong2*>(sW + k * D + 4 * cx);
            #pragma unroll
            for (int r = 0; r < 8; ++r) {
                float a = sH[(ry * 8 + r) * D + k];   // warp-broadcast
                unsigned long long aa = pack2(a, a);
                acc[r][0] = fma2(aa, w.x, acc[r][0]);
                acc[r][1] = fma2(aa, w.y, acc[r][1]);
            }
        }
    };

    auto epilogue_smem = [&]() {
        #pragma unroll
        for (int r = 0; r < 8; ++r) {
            float2 s0 = unpack2(acc[r][0]);
            float2 s1 = unpack2(acc[r][1]);
            float4 v;
            v.x = tanhf(s0.x); v.y = tanhf(s0.y);
            v.z = tanhf(s1.x); v.w = tanhf(s1.y);
            reinterpret_cast<float4*>(sH + (ry * 8 + r) * D)[cx] = v;
        }
    };

    // ====================== Layer 1: [mi, mo, x] @ W1 =====================
    initBias(b1);
    #pragma unroll 1
    for (int p = 0; p < 3; ++p) {
        __syncthreads();                         // prior sW/sH reads complete
        loadH(p == 0 ? (const float*)g_mi : p == 1 ? (const float*)g_mo : x);
        loadW(W1 + (size_t)p * D * D);
        __syncthreads();
        gemm_acc();
    }
    __syncthreads();                             // all sH reads done
    epilogue_smem();

    // ====================== Layers 2..4 ===================================
    const float* Ws[3] = { W2, W3, W4 };
    const float* bs[3] = { b2, b3, b4 };
    #pragma unroll 1
    for (int l = 0; l < 3; ++l) {
        __syncthreads();                         // sH writes visible, prev sW reads done
        loadW(Ws[l]);
        __syncthreads();
        initBias(bs[l]);
        gemm_acc();
        __syncthreads();                         // all sH/sW reads done
        if (l < 2) {
            epilogue_smem();
        } else {
            #pragma unroll
            for (int r = 0; r < 8; ++r) {
                int gr = r0 + ry * 8 + r;
                if (gr < N) {
                    float2 s0 = unpack2(acc[r][0]);
                    float2 s1 = unpack2(acc[r][1]);
                    float4 v;
                    v.x = tanhf(s0.x); v.y = tanhf(s0.y);
                    v.z = tanhf(s1.x); v.w = tanhf(s1.y);
                    reinterpret_cast<float4*>(out + (size_t)gr * D)[cx] = v;
                }
            }
        }
    }
}

// ---------------------------------------------------------------------------
// Host launcher (graph-capturable: kernel launches only)
// ---------------------------------------------------------------------------
extern "C" void kernel_launch(void* const* d_in, const int* in_sizes, int n_in,
                              void* d_out, int out_size) {
    const float* x    = (const float*)d_in[0];
    const float* ew   = (const float*)d_in[1];
    const void*  eidx = d_in[2];
    const float* W1   = (const float*)d_in[3];
    const float* b1   = (const float*)d_in[4];
    const float* W2   = (const float*)d_in[5];
    const float* b2   = (const float*)d_in[6];
    const float* W3   = (const float*)d_in[7];
    const float* b3   = (const float*)d_in[8];
    const float* W4   = (const float*)d_in[9];
    const float* b4   = (const float*)d_in[10];
    float*       out  = (float*)d_out;

    const int N = in_sizes[0] / D;        // 50000
    const int E = in_sizes[2] / 2;        // 800000

    // 0) detect index dtype
    detect_idx_kernel<<<1, 32>>>(eidx, E, N);

    // 1) zero message buffers
    {
        int n4 = N * D / 4;
        zero_kernel<<<(n4 + 255) / 256, 256>>>(n4);
    }

    // 2) edge scatter: one warp per edge
    {
        long long total = (long long)E * 32;
        int blocks = (int)((total + 255) / 256);
        scatter_kernel<<<blocks, 256>>>(x, ew, eidx, E, N);
    }

    // 3) fused MLP
    {
        const int smem = (D * D + TILE_M * D) * (int)sizeof(float);  // 98304 B
        cudaFuncSetAttribute(mlp_kernel,
                             cudaFuncAttributeMaxDynamicSharedMemorySize, smem);
        int blocks = (N + TILE_M - 1) / TILE_M;                      // 782
        mlp_kernel<<<blocks, MLP_THREADS, smem>>>(x, W1, b1, W2, b2,
                                                  W3, b3, W4, b4, out, N);
    }
}